// round 12
// baseline (speedup 1.0000x reference)
#include <cuda_runtime.h>
#include <math.h>
#include <stdint.h>

#define B_ 256
#define L_ 32
#define D_ 512
#define H_ 512

// ---------------- scratch (device globals; no allocation allowed) -----------
__device__ float g_h    [B_ * L_ * H_];   // node h, keyed (batch, slot)
__device__ float g_c    [B_ * L_ * H_];   // node c
__device__ uint4 g_hs   [B_ * L_ * 256];  // node h pre-split (p1,p2,p3,0) per pair
__device__ uint4 g_Wcs  [2560 * 512];     // Wc pre-split per pair (row g*512+j)
__device__ float g_comph[B_ * L_ * H_];   // pair comp h, keyed by LEFT slot
__device__ float g_compc[B_ * L_ * H_];   // pair comp c
__device__ float g_lgpart[B_ * L_ * 32];  // per-16j-slice partial dots
__device__ int   g_order[B_ * L_];        // active slot list per batch
__device__ int4  g_tasks[2 * B_];         // {valid, b, ls, rs} recompute tasks
__device__ float g_part [4 * 512 * 2560]; // split-K partials [ks][task][g*512+j]

__device__ __forceinline__ float sigf(float x) { return 1.0f / (1.0f + expf(-x)); }

// exact 3-way bf16 split of an fp32 pair (truncation: 24 = 8+8+8 mantissa bits)
__device__ __forceinline__ uint32_t split_pair(float x0, float x1, float& r0, float& r1) {
    uint32_t u0 = __float_as_uint(x0) & 0xffff0000u;
    uint32_t u1 = __float_as_uint(x1) & 0xffff0000u;
    r0 = x0 - __uint_as_float(u0);
    r1 = x1 - __uint_as_float(u1);
    return (u0 >> 16) | u1;
}
__device__ __forceinline__ uint4 split3(float x0, float x1) {
    float r0, r1, s0, s1;
    uint32_t p1 = split_pair(x0, x1, r0, r1);
    uint32_t p2 = split_pair(r0, r1, s0, s1);
    uint32_t p3 = (__float_as_uint(s0) >> 16) | (__float_as_uint(s1) & 0xffff0000u);
    return make_uint4(p1, p2, p3, 0u);
}

__device__ __forceinline__ void mma16816(float* d, const uint32_t* a,
                                         uint32_t b0, uint32_t b1) {
    asm volatile(
        "mma.sync.aligned.m16n8k16.row.col.f32.bf16.bf16.f32 "
        "{%0,%1,%2,%3}, {%4,%5,%6,%7}, {%8,%9}, {%0,%1,%2,%3};\n"
        : "+f"(d[0]), "+f"(d[1]), "+f"(d[2]), "+f"(d[3])
        : "r"(a[0]), "r"(a[1]), "r"(a[2]), "r"(a[3]), "r"(b0), "r"(b1));
}

__device__ __forceinline__ void cp16(uint32_t dst, const void* src, int pbytes) {
    asm volatile("cp.async.cg.shared.global [%0], [%1], 16, %2;\n"
                 :: "r"(dst), "l"(src), "r"(pbytes));
}
__device__ __forceinline__ void cp_commit() { asm volatile("cp.async.commit_group;\n"); }
__device__ __forceinline__ void cp_wait(int keep) {
    if (keep) asm volatile("cp.async.wait_group 1;\n" ::: "memory");
    else      asm volatile("cp.async.wait_group 0;\n" ::: "memory");
}

// smem tile addressing: 16 uint4 per row, 1-bit XOR swizzle (write==read formula)
__device__ __forceinline__ int swz(int row, int col) {
    return row * 16 + (col ^ ((row & 1) << 2));
}

// ---------------- init: order[b][j] = j ------------------------------------
__global__ void init_kernel() {
    int idx = blockIdx.x * blockDim.x + threadIdx.x;
    if (idx < B_ * L_) g_order[idx] = idx & 31;
}

// ---------------- pre-split Wc: 2560x1024 fp32 -> uint4 per pair ------------
__global__ void split_wc_kernel(const float* __restrict__ Wc) {
    int idx = blockIdx.x * 256 + threadIdx.x;      // 2560*512
    if (idx < 2560 * 512) {
        float2 v = *(const float2*)&Wc[(size_t)idx * 2];
        g_Wcs[idx] = split3(v.x, v.y);
    }
}

// ---------------- word projection: hc = x @ W_word^T + b_word (fp32) --------
__global__ __launch_bounds__(256) void word_kernel(
    const float* __restrict__ x, const float* __restrict__ Ww,
    const float* __restrict__ bw) {
    __shared__ float Xs[16][132];
    __shared__ float Ws[16][132];
    int tid = threadIdx.x;
    int tx = tid & 15, ty = tid >> 4;
    int m0 = blockIdx.x * 128, n0 = blockIdx.y * 128;

    float acc[8][8];
#pragma unroll
    for (int i = 0; i < 8; i++)
#pragma unroll
        for (int j = 0; j < 8; j++) acc[i][j] = 0.f;

    for (int kc = 0; kc < 32; kc++) {
        int k0 = kc * 16;
#pragma unroll
        for (int rep = 0; rep < 2; rep++) {
            int idx = tid + rep * 256;
            int row = idx >> 2;
            int kq  = (idx & 3) * 4;
            float4 xa = *(const float4*)&x [(size_t)(m0 + row) * 512 + k0 + kq];
            float4 wa = *(const float4*)&Ww[(size_t)(n0 + row) * 512 + k0 + kq];
            Xs[kq + 0][row] = xa.x; Xs[kq + 1][row] = xa.y;
            Xs[kq + 2][row] = xa.z; Xs[kq + 3][row] = xa.w;
            Ws[kq + 0][row] = wa.x; Ws[kq + 1][row] = wa.y;
            Ws[kq + 2][row] = wa.z; Ws[kq + 3][row] = wa.w;
        }
        __syncthreads();
#pragma unroll
        for (int kk = 0; kk < 16; kk++) {
            float a[8], w[8];
#pragma unroll
            for (int i = 0; i < 8; i++) a[i] = Xs[kk][ty * 8 + i];
#pragma unroll
            for (int j = 0; j < 8; j++) w[j] = Ws[kk][tx * 8 + j];
#pragma unroll
            for (int i = 0; i < 8; i++)
#pragma unroll
                for (int j = 0; j < 8; j++) acc[i][j] += a[i] * w[j];
        }
        __syncthreads();
    }
#pragma unroll
    for (int i = 0; i < 8; i++) {
        int m = m0 + ty * 8 + i;
        float vv[8];
#pragma unroll
        for (int j = 0; j < 8; j++) vv[j] = acc[i][j] + bw[n0 + tx * 8 + j];
        if (n0 < 512) {
#pragma unroll
            for (int j = 0; j < 8; j++)
                g_h[(size_t)m * 512 + n0 + tx * 8 + j] = vv[j];
#pragma unroll
            for (int jp = 0; jp < 4; jp++) {
                int col = n0 + tx * 8 + jp * 2;
                g_hs[(size_t)m * 256 + (col >> 1)] = split3(vv[2 * jp], vv[2 * jp + 1]);
            }
        } else {
#pragma unroll
            for (int j = 0; j < 8; j++)
                g_c[(size_t)m * 512 + n0 - 512 + tx * 8 + j] = vv[j];
        }
    }
}

// ---------------- compose GEMM (pre-split, 2-stage cp.async) ----------------
// BM=64 rows, BJ=32 j, 5 gates, BK=32. 8 warps: mw=w&3 (m16), jw=w>>2 (j16).
// smem: A stages 2x[64][16] uint4, B stages 2x[160][16] uint4 (swizzled).
__global__ __launch_bounds__(256) void compose_mma(
    const float* __restrict__ bc, const float* __restrict__ cq,
    int initial, int ntasks) {
    extern __shared__ uint4 dyn[];
    // layout: A0[1024] A1[1024] B0[2560] B1[2560] ints
    int*   sb  = (int*)(dyn + 7168);
    int*   sls = sb + 64;
    int*   srs = sls + 64;
    uint32_t sbase = (uint32_t)__cvta_generic_to_shared(dyn);

    int tid  = threadIdx.x;
    int row0 = blockIdx.x * 64;
    int j0   = blockIdx.y * 32;

    int v = 0;
    if (tid < 64) {
        int t = row0 + tid;
        int b = -1, ls = 0, rs = 0;
        if (t < ntasks) {
            if (initial) { b = t / 31; int p = t - b * 31; ls = p; rs = p + 1; v = 1; }
            else { int4 tk = g_tasks[t]; if (tk.x) { b = tk.y; ls = tk.z; rs = tk.w; v = 1; } }
        }
        sb[tid] = b; sls[tid] = ls; srs[tid] = rs;
    }
    int any = __syncthreads_or(v);
    if (!any) return;

    int lane = tid & 31;
    int warp = tid >> 5;
    int mw = warp & 3;
    int jw = warp >> 2;
    int r = lane >> 2, q = lane & 3;

    float acc[5][2][4];
#pragma unroll
    for (int g = 0; g < 5; g++)
#pragma unroll
        for (int jt = 0; jt < 2; jt++)
#pragma unroll
            for (int e = 0; e < 4; e++) { acc[g][jt][e] = 0.f; }

    auto issue = [&](int kc) {
        int st = kc & 1;
        uint32_t aAddr = sbase + st * 1024 * 16;
        uint32_t bAddr = sbase + (2048 + st * 2560) * 16;
        int left  = (kc < 16);
        int pbase = (kc & 15) * 16;
#pragma unroll
        for (int rep = 0; rep < 4; rep++) {
            int idx = tid + rep * 256;
            int row = idx >> 4, col = idx & 15;
            int b = sb[row];
            const void* src = &g_Wcs[0];
            int pb = 0;
            if (b >= 0) {
                int slot = left ? sls[row] : srs[row];
                src = &g_hs[((size_t)((b << 5) + slot)) * 256 + pbase + col];
                pb = 16;
            }
            cp16(aAddr + swz(row, col) * 16, src, pb);
        }
#pragma unroll
        for (int rep = 0; rep < 10; rep++) {
            int idx = tid + rep * 256;
            int row = idx >> 4, col = idx & 15;          // row 0..159
            int grow = (row >> 5) * 512 + j0 + (row & 31);
            cp16(bAddr + swz(row, col) * 16,
                 &g_Wcs[(size_t)grow * 512 + kc * 16 + col], 16);
        }
        cp_commit();
    };

    issue(0);
    for (int kc = 0; kc < 32; kc++) {
        if (kc + 1 < 32) issue(kc + 1);
        cp_wait(kc + 1 < 32);     // keep the just-issued group in flight
        __syncthreads();

        int st = kc & 1;
        const uint4* cA = dyn + st * 1024;
        const uint4* cB = dyn + 2048 + st * 2560;
#pragma unroll
        for (int t = 0; t < 2; t++) {
            uint4 A0 = cA[swz(mw * 16 + r,     t * 8 + q)];
            uint4 A1 = cA[swz(mw * 16 + r + 8, t * 8 + q)];
            uint4 A2 = cA[swz(mw * 16 + r,     t * 8 + q + 4)];
            uint4 A3 = cA[swz(mw * 16 + r + 8, t * 8 + q + 4)];
            uint32_t a1f[4] = {A0.x, A1.x, A2.x, A3.x};
            uint32_t a2f[4] = {A0.y, A1.y, A2.y, A3.y};
            uint32_t a3f[4] = {A0.z, A1.z, A2.z, A3.z};
#pragma unroll
            for (int g = 0; g < 5; g++) {
#pragma unroll
                for (int jt = 0; jt < 2; jt++) {
                    int col = jw * 16 + jt * 8 + r;
                    uint4 B0 = cB[swz(g * 32 + col, t * 8 + q)];
                    uint4 B1 = cB[swz(g * 32 + col, t * 8 + q + 4)];
                    float* d = acc[g][jt];
                    mma16816(d, a1f, B0.x, B1.x);   // h1*b1
                    mma16816(d, a1f, B0.y, B1.y);   // h1*b2
                    mma16816(d, a2f, B0.x, B1.x);   // h2*b1
                    mma16816(d, a1f, B0.z, B1.z);   // h1*b3
                    mma16816(d, a2f, B0.y, B1.y);   // h2*b2
                    mma16816(d, a3f, B0.x, B1.x);   // h3*b1
                }
            }
        }
        __syncthreads();
    }

    // ------- epilogue: gates -> (h,c) comp + logit partial per 16-j slice ----
#pragma unroll
    for (int half = 0; half < 2; half++) {
        int lrow = mw * 16 + r + half * 8;
        int b = sb[lrow];
        float partial = 0.f;
        if (b >= 0) {
            int ls = sls[lrow], rs = srs[lrow];
            size_t ob = ((size_t)((b << 5) + ls)) * 512;
            size_t rb = ((size_t)((b << 5) + rs)) * 512;
#pragma unroll
            for (int jt = 0; jt < 2; jt++) {
#pragma unroll
                for (int e = 0; e < 2; e++) {
                    int j    = j0 + jw * 16 + jt * 8 + q * 2 + e;
                    int ridx = half * 2 + e;
                    float iv = acc[0][jt][ridx] + bc[0 * 512 + j];
                    float fl = acc[1][jt][ridx] + bc[1 * 512 + j];
                    float fr = acc[2][jt][ridx] + bc[2 * 512 + j];
                    float uu = acc[3][jt][ridx] + bc[3 * 512 + j];
                    float oo = acc[4][jt][ridx] + bc[4 * 512 + j];
                    float cl = g_c[ob + j];
                    float cr = g_c[rb + j];
                    float cn = cl * sigf(fl + 1.f) + cr * sigf(fr + 1.f)
                             + tanhf(uu) * sigf(iv);
                    float hn = sigf(oo) * tanhf(cn);
                    g_compc[ob + j] = cn;
                    g_comph[ob + j] = hn;
                    partial += cq[j] * hn;
                }
            }
        }
        partial += __shfl_xor_sync(0xffffffffu, partial, 1);
        partial += __shfl_xor_sync(0xffffffffu, partial, 2);
        if (q == 0 && b >= 0) {
            int ls = sls[lrow];
            g_lgpart[((b << 5) + ls) * 32 + blockIdx.y * 2 + jw] = partial;
        }
    }
}

// ---------------- split-K step GEMM (pre-split, 2-stage cp.async) -----------
// grid (8, 16, 4): row-block, j-block, k-split. Each k-split does 8 k32-chunks.
__global__ __launch_bounds__(256) void gemm_step() {
    extern __shared__ uint4 dyn[];
    int*   sb  = (int*)(dyn + 7168);
    int*   sls = sb + 64;
    int*   srs = sls + 64;
    uint32_t sbase = (uint32_t)__cvta_generic_to_shared(dyn);

    int tid  = threadIdx.x;
    int row0 = blockIdx.x * 64;
    int j0   = blockIdx.y * 32;
    int ks   = blockIdx.z;
    int kbeg = ks * 8, kend = kbeg + 8;

    int v = 0;
    if (tid < 64) {
        int t = row0 + tid;
        int4 tk = g_tasks[t];
        int b = -1, ls = 0, rs = 0;
        if (tk.x) { b = tk.y; ls = tk.z; rs = tk.w; v = 1; }
        sb[tid] = b; sls[tid] = ls; srs[tid] = rs;
    }
    int any = __syncthreads_or(v);
    if (!any) return;

    int lane = tid & 31;
    int warp = tid >> 5;
    int mw = warp & 3;
    int jw = warp >> 2;
    int r = lane >> 2, q = lane & 3;

    float acc[5][2][4];
#pragma unroll
    for (int g = 0; g < 5; g++)
#pragma unroll
        for (int jt = 0; jt < 2; jt++)
#pragma unroll
            for (int e = 0; e < 4; e++) { acc[g][jt][e] = 0.f; }

    auto issue = [&](int kc) {
        int st = kc & 1;
        uint32_t aAddr = sbase + st * 1024 * 16;
        uint32_t bAddr = sbase + (2048 + st * 2560) * 16;
        int left  = (kc < 16);
        int pbase = (kc & 15) * 16;
#pragma unroll
        for (int rep = 0; rep < 4; rep++) {
            int idx = tid + rep * 256;
            int row = idx >> 4, col = idx & 15;
            int b = sb[row];
            const void* src = &g_Wcs[0];
            int pb = 0;
            if (b >= 0) {
                int slot = left ? sls[row] : srs[row];
                src = &g_hs[((size_t)((b << 5) + slot)) * 256 + pbase + col];
                pb = 16;
            }
            cp16(aAddr + swz(row, col) * 16, src, pb);
        }
#pragma unroll
        for (int rep = 0; rep < 10; rep++) {
            int idx = tid + rep * 256;
            int row = idx >> 4, col = idx & 15;
            int grow = (row >> 5) * 512 + j0 + (row & 31);
            cp16(bAddr + swz(row, col) * 16,
                 &g_Wcs[(size_t)grow * 512 + kc * 16 + col], 16);
        }
        cp_commit();
    };

    issue(kbeg);
    for (int kc = kbeg; kc < kend; kc++) {
        if (kc + 1 < kend) issue(kc + 1);
        cp_wait(kc + 1 < kend);
        __syncthreads();

        int st = kc & 1;
        const uint4* cA = dyn + st * 1024;
        const uint4* cB = dyn + 2048 + st * 2560;
#pragma unroll
        for (int t = 0; t < 2; t++) {
            uint4 A0 = cA[swz(mw * 16 + r,     t * 8 + q)];
            uint4 A1 = cA[swz(mw * 16 + r + 8, t * 8 + q)];
            uint4 A2 = cA[swz(mw * 16 + r,     t * 8 + q + 4)];
            uint4 A3 = cA[swz(mw * 16 + r + 8, t * 8 + q + 4)];
            uint32_t a1f[4] = {A0.x, A1.x, A2.x, A3.x};
            uint32_t a2f[4] = {A0.y, A1.y, A2.y, A3.y};
            uint32_t a3f[4] = {A0.z, A1.z, A2.z, A3.z};
#pragma unroll
            for (int g = 0; g < 5; g++) {
#pragma unroll
                for (int jt = 0; jt < 2; jt++) {
                    int col = jw * 16 + jt * 8 + r;
                    uint4 B0 = cB[swz(g * 32 + col, t * 8 + q)];
                    uint4 B1 = cB[swz(g * 32 + col, t * 8 + q + 4)];
                    float* d = acc[g][jt];
                    mma16816(d, a1f, B0.x, B1.x);
                    mma16816(d, a1f, B0.y, B1.y);
                    mma16816(d, a2f, B0.x, B1.x);
                    mma16816(d, a1f, B0.z, B1.z);
                    mma16816(d, a2f, B0.y, B1.y);
                    mma16816(d, a3f, B0.x, B1.x);
                }
            }
        }
        __syncthreads();
    }

    // write raw partials: g_part[(ks*512 + task)*2560 + g*512 + j]
#pragma unroll
    for (int half = 0; half < 2; half++) {
        int lrow = mw * 16 + r + half * 8;
        if (sb[lrow] >= 0) {
            size_t base = ((size_t)(ks * 512 + row0 + lrow)) * 2560;
#pragma unroll
            for (int g = 0; g < 5; g++)
#pragma unroll
                for (int jt = 0; jt < 2; jt++) {
                    int jbase = j0 + jw * 16 + jt * 8 + q * 2;
                    *(float2*)&g_part[base + g * 512 + jbase] =
                        make_float2(acc[g][jt][half * 2], acc[g][jt][half * 2 + 1]);
                }
        }
    }
}

// ---------------- reduce partials + gate epilogue (one block per task) ------
__global__ __launch_bounds__(256) void reduce_step(const float* __restrict__ bc,
                                                   const float* __restrict__ cq) {
    __shared__ float sp[2][256];
    int t = blockIdx.x;
    int4 tk = g_tasks[t];
    if (!tk.x) return;
    int b = tk.y, ls = tk.z, rs = tk.w;
    int tid = threadIdx.x;
    size_t ob  = ((size_t)((b << 5) + ls)) * 512;
    size_t rbs = ((size_t)((b << 5) + rs)) * 512;

#pragma unroll
    for (int half = 0; half < 2; half++) {
        int j = tid + half * 256;
        float v[5];
#pragma unroll
        for (int g = 0; g < 5; g++) {
            size_t base = (size_t)t * 2560 + g * 512 + j;
            float s0 = g_part[base];
            float s1 = g_part[(size_t)512  * 2560 + base];
            float s2 = g_part[(size_t)1024 * 2560 + base];
            float s3 = g_part[(size_t)1536 * 2560 + base];
            v[g] = ((s0 + s1) + (s2 + s3)) + bc[g * 512 + j];
        }
        float cl = g_c[ob + j], cr = g_c[rbs + j];
        float cn = cl * sigf(v[1] + 1.f) + cr * sigf(v[2] + 1.f)
                 + tanhf(v[3]) * sigf(v[0]);
        float hn = sigf(v[4]) * tanhf(cn);
        g_compc[ob + j] = cn;
        g_comph[ob + j] = hn;
        sp[half][tid] = cq[j] * hn;
    }
    __syncthreads();
    // 32 slices of 16 j each, fixed-order sums (deterministic)
    if (tid < 32) {
        int half = tid >> 4, s16 = tid & 15;
        float s = 0.f;
#pragma unroll
        for (int k = 0; k < 16; k++) s += sp[half][s16 * 16 + k];
        g_lgpart[((b << 5) + ls) * 32 + tid] = s;
    }
}

// ---------------- select + merge (1 CTA per batch) --------------------------
__global__ __launch_bounds__(256) void select_kernel(const int* __restrict__ length,
                                                     int step) {
    int b = blockIdx.x;
    int lane = threadIdx.x & 31;
    int warp = threadIdx.x >> 5;
    __shared__ int sh_active, sh_s;

    if (warp == 0) {
        int len = length[b];
        int active = (step + 1 < len);
        int s = 0;
        if (active) {
            int n    = 32 - step;
            int vlim = len - step - 1;
            int myslot = (lane < n) ? g_order[(b << 5) + lane] : 0;

            float lg = -1e30f;
            if (lane < vlim) {            // deterministic fixed-order sum
                const float* p = &g_lgpart[((b << 5) + myslot) * 32];
                float sum = 0.f;
#pragma unroll
                for (int t = 0; t < 32; t++) sum += p[t];
                lg = sum * 0.04419417382415922f;   // 1/sqrt(512)
            }

            // argmax, first occurrence on ties (matches jnp.argmax)
            float bv = lg; int bi = lane;
#pragma unroll
            for (int off = 16; off; off >>= 1) {
                float ov = __shfl_down_sync(0xffffffffu, bv, off);
                int   oi = __shfl_down_sync(0xffffffffu, bi, off);
                if (ov > bv || (ov == bv && oi < bi)) { bv = ov; bi = oi; }
            }
            int p = __shfl_sync(0xffffffffu, bi, 0);

            s        = __shfl_sync(0xffffffffu, myslot, p);
            int prev = __shfl_sync(0xffffffffu, myslot, (p > 0) ? (p - 1) : 0);
            int nxt2 = __shfl_sync(0xffffffffu, myslot, (p + 2 <= n - 1) ? (p + 2) : 0);
            int nxt  = __shfl_down_sync(0xffffffffu, myslot, 1);

            if (lane >= p + 1 && lane <= n - 2) g_order[(b << 5) + lane] = nxt;
            if (lane == 0) {
                int4 t0 = make_int4(0, 0, 0, 0), t1 = make_int4(0, 0, 0, 0);
                if (p > 0)          t0 = make_int4(1, b, prev, s);
                if (p + 2 <= n - 1) t1 = make_int4(1, b, s, nxt2);
                g_tasks[2 * b]     = t0;
                g_tasks[2 * b + 1] = t1;
            }
        } else if (lane == 0) {
            g_tasks[2 * b]     = make_int4(0, 0, 0, 0);
            g_tasks[2 * b + 1] = make_int4(0, 0, 0, 0);
        }
        if (lane == 0) { sh_active = active; sh_s = s; }
    }
    __syncthreads();
    if (!sh_active) return;

    // merge: node s takes composed value; refresh fp32 + pre-split forms
    int t = threadIdx.x;
    size_t base = ((size_t)((b << 5) + sh_s)) * 512;
    float2 hp = *(const float2*)&g_comph[base + 2 * t];
    float2 cp = *(const float2*)&g_compc[base + 2 * t];
    *(float2*)&g_h[base + 2 * t] = hp;
    *(float2*)&g_c[base + 2 * t] = cp;
    g_hs[((size_t)((b << 5) + sh_s)) * 256 + t] = split3(hp.x, hp.y);
}

// ---------------- output: h of slot 0 of each batch -------------------------
__global__ void out_kernel(float* __restrict__ out) {
    int idx = blockIdx.x * 256 + threadIdx.x;   // 131072 total
    int b = idx >> 9, j = idx & 511;
    out[idx] = g_h[((size_t)b << 14) + j];      // slot 0
}

// ---------------- launch ----------------------------------------------------
extern "C" void kernel_launch(void* const* d_in, const int* in_sizes, int n_in,
                              void* d_out, int out_size) {
    const float* x      = (const float*)d_in[0];
    const int*   length = (const int*)  d_in[1];
    const float* Ww     = (const float*)d_in[2];
    const float* bw     = (const float*)d_in[3];
    const float* Wc     = (const float*)d_in[4];
    const float* bc     = (const float*)d_in[5];
    const float* cq     = (const float*)d_in[6];

    int shmem = 7168 * (int)sizeof(uint4) + 3 * 64 * (int)sizeof(int);  // 115456 B
    static int configured = 0;
    if (!configured) {
        cudaFuncSetAttribute(compose_mma,
                             cudaFuncAttributeMaxDynamicSharedMemorySize, shmem);
        cudaFuncSetAttribute(gemm_step,
                             cudaFuncAttributeMaxDynamicSharedMemorySize, shmem);
        configured = 1;
    }

    init_kernel<<<32, 256>>>();
    split_wc_kernel<<<5120, 256>>>(Wc);
    word_kernel<<<dim3(64, 8), 256>>>(x, Ww, bw);
    // initial compose of all 31 adjacent pairs per batch (7936 rows)
    compose_mma<<<dim3(124, 16), 256, shmem>>>(bc, cq, 1, 7936);
    for (int i = 0; i < 31; i++) {
        select_kernel<<<256, 256>>>(length, i);
        gemm_step<<<dim3(8, 16, 4), 256, shmem>>>();
        reduce_step<<<512, 256>>>(bc, cq);
    }
    out_kernel<<<512, 256>>>((float*)d_out);
    (void)in_sizes; (void)n_in; (void)out_size;
}

// round 13
// speedup vs baseline: 1.0622x; 1.0622x over previous
#include <cuda_runtime.h>
#include <math.h>
#include <stdint.h>

#define B_ 256
#define L_ 32
#define D_ 512
#define H_ 512

// ---------------- scratch (device globals; no allocation allowed) -----------
__device__ float g_h    [B_ * L_ * H_];   // node h, keyed (batch, slot)
__device__ float g_c    [B_ * L_ * H_];   // node c
__device__ uint4 g_hs   [B_ * L_ * 256];  // node h pre-split (p1,p2,p3,0) per pair
__device__ uint4 g_Wcs  [2560 * 512];     // Wc pre-split per pair (row g*512+j)
__device__ float g_comph[B_ * L_ * H_];   // pair comp h, keyed by LEFT slot
__device__ float g_compc[B_ * L_ * H_];   // pair comp c
__device__ float g_lgpart[B_ * L_ * 32];  // per-16j-slice partial dots
__device__ int   g_order[B_ * L_];        // active slot list per batch
__device__ int4  g_tasks[2 * B_];         // {valid, b, ls, rs} recompute tasks
__device__ float g_part [4 * 512 * 2560]; // split-K partials [ks][task][g*512+j]

__device__ __forceinline__ float sigf(float x) { return 1.0f / (1.0f + expf(-x)); }

// exact 3-way bf16 split of an fp32 pair (truncation: 24 = 8+8+8 mantissa bits)
__device__ __forceinline__ uint32_t split_pair(float x0, float x1, float& r0, float& r1) {
    uint32_t u0 = __float_as_uint(x0) & 0xffff0000u;
    uint32_t u1 = __float_as_uint(x1) & 0xffff0000u;
    r0 = x0 - __uint_as_float(u0);
    r1 = x1 - __uint_as_float(u1);
    return (u0 >> 16) | u1;
}
__device__ __forceinline__ uint4 split3(float x0, float x1) {
    float r0, r1, s0, s1;
    uint32_t p1 = split_pair(x0, x1, r0, r1);
    uint32_t p2 = split_pair(r0, r1, s0, s1);
    uint32_t p3 = (__float_as_uint(s0) >> 16) | (__float_as_uint(s1) & 0xffff0000u);
    return make_uint4(p1, p2, p3, 0u);
}

__device__ __forceinline__ void mma16816(float* d, const uint32_t* a,
                                         uint32_t b0, uint32_t b1) {
    asm volatile(
        "mma.sync.aligned.m16n8k16.row.col.f32.bf16.bf16.f32 "
        "{%0,%1,%2,%3}, {%4,%5,%6,%7}, {%8,%9}, {%0,%1,%2,%3};\n"
        : "+f"(d[0]), "+f"(d[1]), "+f"(d[2]), "+f"(d[3])
        : "r"(a[0]), "r"(a[1]), "r"(a[2]), "r"(a[3]), "r"(b0), "r"(b1));
}

__device__ __forceinline__ void cp16(uint32_t dst, const void* src, int pbytes) {
    asm volatile("cp.async.cg.shared.global [%0], [%1], 16, %2;\n"
                 :: "r"(dst), "l"(src), "r"(pbytes));
}
__device__ __forceinline__ void cp_commit() { asm volatile("cp.async.commit_group;\n"); }
__device__ __forceinline__ void cp_wait(int keep) {
    if (keep) asm volatile("cp.async.wait_group 1;\n" ::: "memory");
    else      asm volatile("cp.async.wait_group 0;\n" ::: "memory");
}

// smem tile addressing: 16 uint4 per row, 1-bit XOR swizzle (write==read formula)
__device__ __forceinline__ int swz(int row, int col) {
    return row * 16 + (col ^ ((row & 1) << 2));
}

// ---------------- init: order[b][j] = j ------------------------------------
__global__ void init_kernel() {
    int idx = blockIdx.x * blockDim.x + threadIdx.x;
    if (idx < B_ * L_) g_order[idx] = idx & 31;
}

// ---------------- pre-split Wc: 2560x1024 fp32 -> uint4 per pair ------------
__global__ void split_wc_kernel(const float* __restrict__ Wc) {
    int idx = blockIdx.x * 256 + threadIdx.x;      // 2560*512
    if (idx < 2560 * 512) {
        float2 v = *(const float2*)&Wc[(size_t)idx * 2];
        g_Wcs[idx] = split3(v.x, v.y);
    }
}

// ---------------- word projection: hc = x @ W_word^T + b_word (fp32) --------
__global__ __launch_bounds__(256) void word_kernel(
    const float* __restrict__ x, const float* __restrict__ Ww,
    const float* __restrict__ bw) {
    __shared__ float Xs[16][132];
    __shared__ float Ws[16][132];
    int tid = threadIdx.x;
    int tx = tid & 15, ty = tid >> 4;
    int m0 = blockIdx.x * 128, n0 = blockIdx.y * 128;

    float acc[8][8];
#pragma unroll
    for (int i = 0; i < 8; i++)
#pragma unroll
        for (int j = 0; j < 8; j++) acc[i][j] = 0.f;

    for (int kc = 0; kc < 32; kc++) {
        int k0 = kc * 16;
#pragma unroll
        for (int rep = 0; rep < 2; rep++) {
            int idx = tid + rep * 256;
            int row = idx >> 2;
            int kq  = (idx & 3) * 4;
            float4 xa = *(const float4*)&x [(size_t)(m0 + row) * 512 + k0 + kq];
            float4 wa = *(const float4*)&Ww[(size_t)(n0 + row) * 512 + k0 + kq];
            Xs[kq + 0][row] = xa.x; Xs[kq + 1][row] = xa.y;
            Xs[kq + 2][row] = xa.z; Xs[kq + 3][row] = xa.w;
            Ws[kq + 0][row] = wa.x; Ws[kq + 1][row] = wa.y;
            Ws[kq + 2][row] = wa.z; Ws[kq + 3][row] = wa.w;
        }
        __syncthreads();
#pragma unroll
        for (int kk = 0; kk < 16; kk++) {
            float a[8], w[8];
#pragma unroll
            for (int i = 0; i < 8; i++) a[i] = Xs[kk][ty * 8 + i];
#pragma unroll
            for (int j = 0; j < 8; j++) w[j] = Ws[kk][tx * 8 + j];
#pragma unroll
            for (int i = 0; i < 8; i++)
#pragma unroll
                for (int j = 0; j < 8; j++) acc[i][j] += a[i] * w[j];
        }
        __syncthreads();
    }
#pragma unroll
    for (int i = 0; i < 8; i++) {
        int m = m0 + ty * 8 + i;
        float vv[8];
#pragma unroll
        for (int j = 0; j < 8; j++) vv[j] = acc[i][j] + bw[n0 + tx * 8 + j];
        if (n0 < 512) {
#pragma unroll
            for (int j = 0; j < 8; j++)
                g_h[(size_t)m * 512 + n0 + tx * 8 + j] = vv[j];
#pragma unroll
            for (int jp = 0; jp < 4; jp++) {
                int col = n0 + tx * 8 + jp * 2;
                g_hs[(size_t)m * 256 + (col >> 1)] = split3(vv[2 * jp], vv[2 * jp + 1]);
            }
        } else {
#pragma unroll
            for (int j = 0; j < 8; j++)
                g_c[(size_t)m * 512 + n0 - 512 + tx * 8 + j] = vv[j];
        }
    }
}

// ---------------- compose GEMM (pre-split, 2-stage cp.async) ----------------
// BM=64 rows, BJ=32 j, 5 gates, BK=32. 8 warps: mw=w&3 (m16), jw=w>>2 (j16).
// smem: A stages 2x[64][16] uint4, B stages 2x[160][16] uint4 (swizzled).
__global__ __launch_bounds__(256, 2) void compose_mma(
    const float* __restrict__ bc, const float* __restrict__ cq,
    int initial, int ntasks) {
    extern __shared__ uint4 dyn[];
    // layout: A0[1024] A1[1024] B0[2560] B1[2560] ints
    int*   sb  = (int*)(dyn + 7168);
    int*   sls = sb + 64;
    int*   srs = sls + 64;
    uint32_t sbase = (uint32_t)__cvta_generic_to_shared(dyn);

    int tid  = threadIdx.x;
    int row0 = blockIdx.x * 64;
    int j0   = blockIdx.y * 32;

    int v = 0;
    if (tid < 64) {
        int t = row0 + tid;
        int b = -1, ls = 0, rs = 0;
        if (t < ntasks) {
            if (initial) { b = t / 31; int p = t - b * 31; ls = p; rs = p + 1; v = 1; }
            else { int4 tk = g_tasks[t]; if (tk.x) { b = tk.y; ls = tk.z; rs = tk.w; v = 1; } }
        }
        sb[tid] = b; sls[tid] = ls; srs[tid] = rs;
    }
    int any = __syncthreads_or(v);
    if (!any) return;

    int lane = tid & 31;
    int warp = tid >> 5;
    int mw = warp & 3;
    int jw = warp >> 2;
    int r = lane >> 2, q = lane & 3;

    float acc[5][2][4];
#pragma unroll
    for (int g = 0; g < 5; g++)
#pragma unroll
        for (int jt = 0; jt < 2; jt++)
#pragma unroll
            for (int e = 0; e < 4; e++) { acc[g][jt][e] = 0.f; }

    auto issue = [&](int kc) {
        int st = kc & 1;
        uint32_t aAddr = sbase + st * 1024 * 16;
        uint32_t bAddr = sbase + (2048 + st * 2560) * 16;
        int left  = (kc < 16);
        int pbase = (kc & 15) * 16;
#pragma unroll
        for (int rep = 0; rep < 4; rep++) {
            int idx = tid + rep * 256;
            int row = idx >> 4, col = idx & 15;
            int b = sb[row];
            const void* src = &g_Wcs[0];
            int pb = 0;
            if (b >= 0) {
                int slot = left ? sls[row] : srs[row];
                src = &g_hs[((size_t)((b << 5) + slot)) * 256 + pbase + col];
                pb = 16;
            }
            cp16(aAddr + swz(row, col) * 16, src, pb);
        }
#pragma unroll
        for (int rep = 0; rep < 10; rep++) {
            int idx = tid + rep * 256;
            int row = idx >> 4, col = idx & 15;          // row 0..159
            int grow = (row >> 5) * 512 + j0 + (row & 31);
            cp16(bAddr + swz(row, col) * 16,
                 &g_Wcs[(size_t)grow * 512 + kc * 16 + col], 16);
        }
        cp_commit();
    };

    issue(0);
    for (int kc = 0; kc < 32; kc++) {
        if (kc + 1 < 32) issue(kc + 1);
        cp_wait(kc + 1 < 32);     // keep the just-issued group in flight
        __syncthreads();

        int st = kc & 1;
        const uint4* cA = dyn + st * 1024;
        const uint4* cB = dyn + 2048 + st * 2560;
#pragma unroll
        for (int t = 0; t < 2; t++) {
            uint4 A0 = cA[swz(mw * 16 + r,     t * 8 + q)];
            uint4 A1 = cA[swz(mw * 16 + r + 8, t * 8 + q)];
            uint4 A2 = cA[swz(mw * 16 + r,     t * 8 + q + 4)];
            uint4 A3 = cA[swz(mw * 16 + r + 8, t * 8 + q + 4)];
            uint32_t a1f[4] = {A0.x, A1.x, A2.x, A3.x};
            uint32_t a2f[4] = {A0.y, A1.y, A2.y, A3.y};
            uint32_t a3f[4] = {A0.z, A1.z, A2.z, A3.z};
#pragma unroll
            for (int g = 0; g < 5; g++) {
#pragma unroll
                for (int jt = 0; jt < 2; jt++) {
                    int col = jw * 16 + jt * 8 + r;
                    uint4 B0 = cB[swz(g * 32 + col, t * 8 + q)];
                    uint4 B1 = cB[swz(g * 32 + col, t * 8 + q + 4)];
                    float* d = acc[g][jt];
                    mma16816(d, a1f, B0.x, B1.x);   // h1*b1
                    mma16816(d, a1f, B0.y, B1.y);   // h1*b2
                    mma16816(d, a2f, B0.x, B1.x);   // h2*b1
                    mma16816(d, a1f, B0.z, B1.z);   // h1*b3
                    mma16816(d, a2f, B0.y, B1.y);   // h2*b2
                    mma16816(d, a3f, B0.x, B1.x);   // h3*b1
                }
            }
        }
        __syncthreads();
    }

    // ------- epilogue: gates -> (h,c) comp + logit partial per 16-j slice ----
#pragma unroll
    for (int half = 0; half < 2; half++) {
        int lrow = mw * 16 + r + half * 8;
        int b = sb[lrow];
        float partial = 0.f;
        if (b >= 0) {
            int ls = sls[lrow], rs = srs[lrow];
            size_t ob = ((size_t)((b << 5) + ls)) * 512;
            size_t rb = ((size_t)((b << 5) + rs)) * 512;
#pragma unroll
            for (int jt = 0; jt < 2; jt++) {
#pragma unroll
                for (int e = 0; e < 2; e++) {
                    int j    = j0 + jw * 16 + jt * 8 + q * 2 + e;
                    int ridx = half * 2 + e;
                    float iv = acc[0][jt][ridx] + bc[0 * 512 + j];
                    float fl = acc[1][jt][ridx] + bc[1 * 512 + j];
                    float fr = acc[2][jt][ridx] + bc[2 * 512 + j];
                    float uu = acc[3][jt][ridx] + bc[3 * 512 + j];
                    float oo = acc[4][jt][ridx] + bc[4 * 512 + j];
                    float cl = g_c[ob + j];
                    float cr = g_c[rb + j];
                    float cn = cl * sigf(fl + 1.f) + cr * sigf(fr + 1.f)
                             + tanhf(uu) * sigf(iv);
                    float hn = sigf(oo) * tanhf(cn);
                    g_compc[ob + j] = cn;
                    g_comph[ob + j] = hn;
                    partial += cq[j] * hn;
                }
            }
        }
        partial += __shfl_xor_sync(0xffffffffu, partial, 1);
        partial += __shfl_xor_sync(0xffffffffu, partial, 2);
        if (q == 0 && b >= 0) {
            int ls = sls[lrow];
            g_lgpart[((b << 5) + ls) * 32 + blockIdx.y * 2 + jw] = partial;
        }
    }
}

// ---------------- split-K step GEMM (pre-split, 2-stage cp.async) -----------
// grid (8, 16, 4): row-block, j-block, k-split. Each k-split does 8 k32-chunks.
__global__ __launch_bounds__(256, 2) void gemm_step() {
    extern __shared__ uint4 dyn[];
    int*   sb  = (int*)(dyn + 7168);
    int*   sls = sb + 64;
    int*   srs = sls + 64;
    uint32_t sbase = (uint32_t)__cvta_generic_to_shared(dyn);

    int tid  = threadIdx.x;
    int row0 = blockIdx.x * 64;
    int j0   = blockIdx.y * 32;
    int ks   = blockIdx.z;
    int kbeg = ks * 8, kend = kbeg + 8;

    int v = 0;
    if (tid < 64) {
        int t = row0 + tid;
        int4 tk = g_tasks[t];
        int b = -1, ls = 0, rs = 0;
        if (tk.x) { b = tk.y; ls = tk.z; rs = tk.w; v = 1; }
        sb[tid] = b; sls[tid] = ls; srs[tid] = rs;
    }
    int any = __syncthreads_or(v);
    if (!any) return;

    int lane = tid & 31;
    int warp = tid >> 5;
    int mw = warp & 3;
    int jw = warp >> 2;
    int r = lane >> 2, q = lane & 3;

    float acc[5][2][4];
#pragma unroll
    for (int g = 0; g < 5; g++)
#pragma unroll
        for (int jt = 0; jt < 2; jt++)
#pragma unroll
            for (int e = 0; e < 4; e++) { acc[g][jt][e] = 0.f; }

    auto issue = [&](int kc) {
        int st = kc & 1;
        uint32_t aAddr = sbase + st * 1024 * 16;
        uint32_t bAddr = sbase + (2048 + st * 2560) * 16;
        int left  = (kc < 16);
        int pbase = (kc & 15) * 16;
#pragma unroll
        for (int rep = 0; rep < 4; rep++) {
            int idx = tid + rep * 256;
            int row = idx >> 4, col = idx & 15;
            int b = sb[row];
            const void* src = &g_Wcs[0];
            int pb = 0;
            if (b >= 0) {
                int slot = left ? sls[row] : srs[row];
                src = &g_hs[((size_t)((b << 5) + slot)) * 256 + pbase + col];
                pb = 16;
            }
            cp16(aAddr + swz(row, col) * 16, src, pb);
        }
#pragma unroll
        for (int rep = 0; rep < 10; rep++) {
            int idx = tid + rep * 256;
            int row = idx >> 4, col = idx & 15;
            int grow = (row >> 5) * 512 + j0 + (row & 31);
            cp16(bAddr + swz(row, col) * 16,
                 &g_Wcs[(size_t)grow * 512 + kc * 16 + col], 16);
        }
        cp_commit();
    };

    issue(kbeg);
    for (int kc = kbeg; kc < kend; kc++) {
        if (kc + 1 < kend) issue(kc + 1);
        cp_wait(kc + 1 < kend);
        __syncthreads();

        int st = kc & 1;
        const uint4* cA = dyn + st * 1024;
        const uint4* cB = dyn + 2048 + st * 2560;
#pragma unroll
        for (int t = 0; t < 2; t++) {
            uint4 A0 = cA[swz(mw * 16 + r,     t * 8 + q)];
            uint4 A1 = cA[swz(mw * 16 + r + 8, t * 8 + q)];
            uint4 A2 = cA[swz(mw * 16 + r,     t * 8 + q + 4)];
            uint4 A3 = cA[swz(mw * 16 + r + 8, t * 8 + q + 4)];
            uint32_t a1f[4] = {A0.x, A1.x, A2.x, A3.x};
            uint32_t a2f[4] = {A0.y, A1.y, A2.y, A3.y};
            uint32_t a3f[4] = {A0.z, A1.z, A2.z, A3.z};
#pragma unroll
            for (int g = 0; g < 5; g++) {
#pragma unroll
                for (int jt = 0; jt < 2; jt++) {
                    int col = jw * 16 + jt * 8 + r;
                    uint4 B0 = cB[swz(g * 32 + col, t * 8 + q)];
                    uint4 B1 = cB[swz(g * 32 + col, t * 8 + q + 4)];
                    float* d = acc[g][jt];
                    mma16816(d, a1f, B0.x, B1.x);
                    mma16816(d, a1f, B0.y, B1.y);
                    mma16816(d, a2f, B0.x, B1.x);
                    mma16816(d, a1f, B0.z, B1.z);
                    mma16816(d, a2f, B0.y, B1.y);
                    mma16816(d, a3f, B0.x, B1.x);
                }
            }
        }
        __syncthreads();
    }

    // write raw partials: g_part[(ks*512 + task)*2560 + g*512 + j]
#pragma unroll
    for (int half = 0; half < 2; half++) {
        int lrow = mw * 16 + r + half * 8;
        if (sb[lrow] >= 0) {
            size_t base = ((size_t)(ks * 512 + row0 + lrow)) * 2560;
#pragma unroll
            for (int g = 0; g < 5; g++)
#pragma unroll
                for (int jt = 0; jt < 2; jt++) {
                    int jbase = j0 + jw * 16 + jt * 8 + q * 2;
                    *(float2*)&g_part[base + g * 512 + jbase] =
                        make_float2(acc[g][jt][half * 2], acc[g][jt][half * 2 + 1]);
                }
        }
    }
}

// ---------------- reduce partials + gate epilogue (one block per task) ------
__global__ __launch_bounds__(256) void reduce_step(const float* __restrict__ bc,
                                                   const float* __restrict__ cq) {
    __shared__ float sp[2][256];
    int t = blockIdx.x;
    int4 tk = g_tasks[t];
    if (!tk.x) return;
    int b = tk.y, ls = tk.z, rs = tk.w;
    int tid = threadIdx.x;
    size_t ob  = ((size_t)((b << 5) + ls)) * 512;
    size_t rbs = ((size_t)((b << 5) + rs)) * 512;

#pragma unroll
    for (int half = 0; half < 2; half++) {
        int j = tid + half * 256;
        float v[5];
#pragma unroll
        for (int g = 0; g < 5; g++) {
            size_t base = (size_t)t * 2560 + g * 512 + j;
            float s0 = g_part[base];
            float s1 = g_part[(size_t)512  * 2560 + base];
            float s2 = g_part[(size_t)1024 * 2560 + base];
            float s3 = g_part[(size_t)1536 * 2560 + base];
            v[g] = ((s0 + s1) + (s2 + s3)) + bc[g * 512 + j];
        }
        float cl = g_c[ob + j], cr = g_c[rbs + j];
        float cn = cl * sigf(v[1] + 1.f) + cr * sigf(v[2] + 1.f)
                 + tanhf(v[3]) * sigf(v[0]);
        float hn = sigf(v[4]) * tanhf(cn);
        g_compc[ob + j] = cn;
        g_comph[ob + j] = hn;
        sp[half][tid] = cq[j] * hn;
    }
    __syncthreads();
    // 32 slices of 16 j each, fixed-order sums (deterministic)
    if (tid < 32) {
        int half = tid >> 4, s16 = tid & 15;
        float s = 0.f;
#pragma unroll
        for (int k = 0; k < 16; k++) s += sp[half][s16 * 16 + k];
        g_lgpart[((b << 5) + ls) * 32 + tid] = s;
    }
}

// ---------------- select + merge (1 CTA per batch) --------------------------
__global__ __launch_bounds__(256) void select_kernel(const int* __restrict__ length,
                                                     int step) {
    int b = blockIdx.x;
    int lane = threadIdx.x & 31;
    int warp = threadIdx.x >> 5;
    __shared__ int sh_active, sh_s;

    if (warp == 0) {
        int len = length[b];
        int active = (step + 1 < len);
        int s = 0;
        if (active) {
            int n    = 32 - step;
            int vlim = len - step - 1;
            int myslot = (lane < n) ? g_order[(b << 5) + lane] : 0;

            float lg = -1e30f;
            if (lane < vlim) {            // deterministic fixed-order sum
                const float* p = &g_lgpart[((b << 5) + myslot) * 32];
                float sum = 0.f;
#pragma unroll
                for (int t = 0; t < 32; t++) sum += p[t];
                lg = sum * 0.04419417382415922f;   // 1/sqrt(512)
            }

            // argmax, first occurrence on ties (matches jnp.argmax)
            float bv = lg; int bi = lane;
#pragma unroll
            for (int off = 16; off; off >>= 1) {
                float ov = __shfl_down_sync(0xffffffffu, bv, off);
                int   oi = __shfl_down_sync(0xffffffffu, bi, off);
                if (ov > bv || (ov == bv && oi < bi)) { bv = ov; bi = oi; }
            }
            int p = __shfl_sync(0xffffffffu, bi, 0);

            s        = __shfl_sync(0xffffffffu, myslot, p);
            int prev = __shfl_sync(0xffffffffu, myslot, (p > 0) ? (p - 1) : 0);
            int nxt2 = __shfl_sync(0xffffffffu, myslot, (p + 2 <= n - 1) ? (p + 2) : 0);
            int nxt  = __shfl_down_sync(0xffffffffu, myslot, 1);

            if (lane >= p + 1 && lane <= n - 2) g_order[(b << 5) + lane] = nxt;
            if (lane == 0) {
                int4 t0 = make_int4(0, 0, 0, 0), t1 = make_int4(0, 0, 0, 0);
                if (p > 0)          t0 = make_int4(1, b, prev, s);
                if (p + 2 <= n - 1) t1 = make_int4(1, b, s, nxt2);
                g_tasks[2 * b]     = t0;
                g_tasks[2 * b + 1] = t1;
            }
        } else if (lane == 0) {
            g_tasks[2 * b]     = make_int4(0, 0, 0, 0);
            g_tasks[2 * b + 1] = make_int4(0, 0, 0, 0);
        }
        if (lane == 0) { sh_active = active; sh_s = s; }
    }
    __syncthreads();
    if (!sh_active) return;

    // merge: node s takes composed value; refresh fp32 + pre-split forms
    int t = threadIdx.x;
    size_t base = ((size_t)((b << 5) + sh_s)) * 512;
    float2 hp = *(const float2*)&g_comph[base + 2 * t];
    float2 cp = *(const float2*)&g_compc[base + 2 * t];
    *(float2*)&g_h[base + 2 * t] = hp;
    *(float2*)&g_c[base + 2 * t] = cp;
    g_hs[((size_t)((b << 5) + sh_s)) * 256 + t] = split3(hp.x, hp.y);
}

// ---------------- output: h of slot 0 of each batch -------------------------
__global__ void out_kernel(float* __restrict__ out) {
    int idx = blockIdx.x * 256 + threadIdx.x;   // 131072 total
    int b = idx >> 9, j = idx & 511;
    out[idx] = g_h[((size_t)b << 14) + j];      // slot 0
}

// ---------------- launch ----------------------------------------------------
extern "C" void kernel_launch(void* const* d_in, const int* in_sizes, int n_in,
                              void* d_out, int out_size) {
    const float* x      = (const float*)d_in[0];
    const int*   length = (const int*)  d_in[1];
    const float* Ww     = (const float*)d_in[2];
    const float* bw     = (const float*)d_in[3];
    const float* Wc     = (const float*)d_in[4];
    const float* bc     = (const float*)d_in[5];
    const float* cq     = (const float*)d_in[6];

    int shmem = 7168 * (int)sizeof(uint4) + 3 * 64 * (int)sizeof(int);  // 115456 B
    static int configured = 0;
    if (!configured) {
        cudaFuncSetAttribute(compose_mma,
                             cudaFuncAttributeMaxDynamicSharedMemorySize, shmem);
        cudaFuncSetAttribute(gemm_step,
                             cudaFuncAttributeMaxDynamicSharedMemorySize, shmem);
        configured = 1;
    }

    init_kernel<<<32, 256>>>();
    split_wc_kernel<<<5120, 256>>>(Wc);
    word_kernel<<<dim3(64, 8), 256>>>(x, Ww, bw);
    // initial compose of all 31 adjacent pairs per batch (7936 rows)
    compose_mma<<<dim3(124, 16), 256, shmem>>>(bc, cq, 1, 7936);
    for (int i = 0; i < 31; i++) {
        select_kernel<<<256, 256>>>(length, i);
        gemm_step<<<dim3(8, 16, 4), 256, shmem>>>();
        reduce_step<<<512, 256>>>(bc, cq);
    }
    out_kernel<<<512, 256>>>((float*)d_out);
    (void)in_sizes; (void)n_in; (void)out_size;
}

// round 14
// speedup vs baseline: 1.2427x; 1.1700x over previous
#include <cuda_runtime.h>
#include <math.h>
#include <stdint.h>

#define B_ 256
#define L_ 32
#define D_ 512
#define H_ 512

// ---------------- scratch (device globals; no allocation allowed) -----------
__device__ float g_h    [B_ * L_ * H_];   // node h, keyed (batch, slot)
__device__ float g_c    [B_ * L_ * H_];   // node c
__device__ uint4 g_hs   [B_ * L_ * 256];  // node h pre-split (p1,p2,p3,0) per pair
__device__ uint4 g_Wcs  [2560 * 512];     // Wc pre-split per pair (row g*512+j)
__device__ float g_comph[B_ * L_ * H_];   // pair comp h, keyed by LEFT slot
__device__ float g_compc[B_ * L_ * H_];   // pair comp c
__device__ float g_lgpart[B_ * L_ * 32];  // per-16j-slice partial dots
__device__ int   g_order[B_ * L_];        // active slot list per batch
__device__ int4  g_tasks[2 * B_];         // {valid, b, ls, rs} per-batch slots
__device__ int4  g_ctasks[2 * B_];        // compacted tasks (stable order)
__device__ int   g_ntasks;                // number of compacted tasks
__device__ float g_part [4 * 512 * 2560]; // split-K partials [ks][ctask][g*512+j]

__device__ __forceinline__ float sigf(float x) { return 1.0f / (1.0f + expf(-x)); }

// exact 3-way bf16 split of an fp32 pair (truncation: 24 = 8+8+8 mantissa bits)
__device__ __forceinline__ uint32_t split_pair(float x0, float x1, float& r0, float& r1) {
    uint32_t u0 = __float_as_uint(x0) & 0xffff0000u;
    uint32_t u1 = __float_as_uint(x1) & 0xffff0000u;
    r0 = x0 - __uint_as_float(u0);
    r1 = x1 - __uint_as_float(u1);
    return (u0 >> 16) | u1;
}
__device__ __forceinline__ uint4 split3(float x0, float x1) {
    float r0, r1, s0, s1;
    uint32_t p1 = split_pair(x0, x1, r0, r1);
    uint32_t p2 = split_pair(r0, r1, s0, s1);
    uint32_t p3 = (__float_as_uint(s0) >> 16) | (__float_as_uint(s1) & 0xffff0000u);
    return make_uint4(p1, p2, p3, 0u);
}

__device__ __forceinline__ void mma16816(float* d, const uint32_t* a,
                                         uint32_t b0, uint32_t b1) {
    asm volatile(
        "mma.sync.aligned.m16n8k16.row.col.f32.bf16.bf16.f32 "
        "{%0,%1,%2,%3}, {%4,%5,%6,%7}, {%8,%9}, {%0,%1,%2,%3};\n"
        : "+f"(d[0]), "+f"(d[1]), "+f"(d[2]), "+f"(d[3])
        : "r"(a[0]), "r"(a[1]), "r"(a[2]), "r"(a[3]), "r"(b0), "r"(b1));
}

__device__ __forceinline__ void cp16(uint32_t dst, const void* src, int pbytes) {
    asm volatile("cp.async.cg.shared.global [%0], [%1], 16, %2;\n"
                 :: "r"(dst), "l"(src), "r"(pbytes));
}
__device__ __forceinline__ void cp_commit() { asm volatile("cp.async.commit_group;\n"); }
__device__ __forceinline__ void cp_wait(int keep) {
    if (keep) asm volatile("cp.async.wait_group 1;\n" ::: "memory");
    else      asm volatile("cp.async.wait_group 0;\n" ::: "memory");
}

// smem tile addressing: 16 uint4 per row, 1-bit XOR swizzle (write==read formula)
__device__ __forceinline__ int swz(int row, int col) {
    return row * 16 + (col ^ ((row & 1) << 2));
}

// ---------------- init: order[b][j] = j ------------------------------------
__global__ void init_kernel() {
    int idx = blockIdx.x * blockDim.x + threadIdx.x;
    if (idx < B_ * L_) g_order[idx] = idx & 31;
}

// ---------------- pre-split Wc: 2560x1024 fp32 -> uint4 per pair ------------
__global__ void split_wc_kernel(const float* __restrict__ Wc) {
    int idx = blockIdx.x * 256 + threadIdx.x;      // 2560*512
    if (idx < 2560 * 512) {
        float2 v = *(const float2*)&Wc[(size_t)idx * 2];
        g_Wcs[idx] = split3(v.x, v.y);
    }
}

// ---------------- word projection: hc = x @ W_word^T + b_word (fp32) --------
__global__ __launch_bounds__(256) void word_kernel(
    const float* __restrict__ x, const float* __restrict__ Ww,
    const float* __restrict__ bw) {
    __shared__ float Xs[16][132];
    __shared__ float Ws[16][132];
    int tid = threadIdx.x;
    int tx = tid & 15, ty = tid >> 4;
    int m0 = blockIdx.x * 128, n0 = blockIdx.y * 128;

    float acc[8][8];
#pragma unroll
    for (int i = 0; i < 8; i++)
#pragma unroll
        for (int j = 0; j < 8; j++) acc[i][j] = 0.f;

    for (int kc = 0; kc < 32; kc++) {
        int k0 = kc * 16;
#pragma unroll
        for (int rep = 0; rep < 2; rep++) {
            int idx = tid + rep * 256;
            int row = idx >> 2;
            int kq  = (idx & 3) * 4;
            float4 xa = *(const float4*)&x [(size_t)(m0 + row) * 512 + k0 + kq];
            float4 wa = *(const float4*)&Ww[(size_t)(n0 + row) * 512 + k0 + kq];
            Xs[kq + 0][row] = xa.x; Xs[kq + 1][row] = xa.y;
            Xs[kq + 2][row] = xa.z; Xs[kq + 3][row] = xa.w;
            Ws[kq + 0][row] = wa.x; Ws[kq + 1][row] = wa.y;
            Ws[kq + 2][row] = wa.z; Ws[kq + 3][row] = wa.w;
        }
        __syncthreads();
#pragma unroll
        for (int kk = 0; kk < 16; kk++) {
            float a[8], w[8];
#pragma unroll
            for (int i = 0; i < 8; i++) a[i] = Xs[kk][ty * 8 + i];
#pragma unroll
            for (int j = 0; j < 8; j++) w[j] = Ws[kk][tx * 8 + j];
#pragma unroll
            for (int i = 0; i < 8; i++)
#pragma unroll
                for (int j = 0; j < 8; j++) acc[i][j] += a[i] * w[j];
        }
        __syncthreads();
    }
#pragma unroll
    for (int i = 0; i < 8; i++) {
        int m = m0 + ty * 8 + i;
        float vv[8];
#pragma unroll
        for (int j = 0; j < 8; j++) vv[j] = acc[i][j] + bw[n0 + tx * 8 + j];
        if (n0 < 512) {
#pragma unroll
            for (int j = 0; j < 8; j++)
                g_h[(size_t)m * 512 + n0 + tx * 8 + j] = vv[j];
#pragma unroll
            for (int jp = 0; jp < 4; jp++) {
                int col = n0 + tx * 8 + jp * 2;
                g_hs[(size_t)m * 256 + (col >> 1)] = split3(vv[2 * jp], vv[2 * jp + 1]);
            }
        } else {
#pragma unroll
            for (int j = 0; j < 8; j++)
                g_c[(size_t)m * 512 + n0 - 512 + tx * 8 + j] = vv[j];
        }
    }
}

// ---------------- compose GEMM (pre-split, 2-stage cp.async) ----------------
// BM=64 rows, BJ=32 j, 5 gates, BK=32. 8 warps: mw=w&3 (m16), jw=w>>2 (j16).
__global__ __launch_bounds__(256, 2) void compose_mma(
    const float* __restrict__ bc, const float* __restrict__ cq,
    int initial, int ntasks) {
    extern __shared__ uint4 dyn[];
    int*   sb  = (int*)(dyn + 7168);
    int*   sls = sb + 64;
    int*   srs = sls + 64;
    uint32_t sbase = (uint32_t)__cvta_generic_to_shared(dyn);

    int tid  = threadIdx.x;
    int row0 = blockIdx.x * 64;
    int j0   = blockIdx.y * 32;

    int v = 0;
    if (tid < 64) {
        int t = row0 + tid;
        int b = -1, ls = 0, rs = 0;
        if (t < ntasks) {
            if (initial) { b = t / 31; int p = t - b * 31; ls = p; rs = p + 1; v = 1; }
            else { int4 tk = g_ctasks[t]; b = tk.y; ls = tk.z; rs = tk.w; v = 1; }
        }
        sb[tid] = b; sls[tid] = ls; srs[tid] = rs;
    }
    int any = __syncthreads_or(v);
    if (!any) return;

    int lane = tid & 31;
    int warp = tid >> 5;
    int mw = warp & 3;
    int jw = warp >> 2;
    int r = lane >> 2, q = lane & 3;

    float acc[5][2][4];
#pragma unroll
    for (int g = 0; g < 5; g++)
#pragma unroll
        for (int jt = 0; jt < 2; jt++)
#pragma unroll
            for (int e = 0; e < 4; e++) { acc[g][jt][e] = 0.f; }

    auto issue = [&](int kc) {
        int st = kc & 1;
        uint32_t aAddr = sbase + st * 1024 * 16;
        uint32_t bAddr = sbase + (2048 + st * 2560) * 16;
        int left  = (kc < 16);
        int pbase = (kc & 15) * 16;
#pragma unroll
        for (int rep = 0; rep < 4; rep++) {
            int idx = tid + rep * 256;
            int row = idx >> 4, col = idx & 15;
            int b = sb[row];
            const void* src = &g_Wcs[0];
            int pb = 0;
            if (b >= 0) {
                int slot = left ? sls[row] : srs[row];
                src = &g_hs[((size_t)((b << 5) + slot)) * 256 + pbase + col];
                pb = 16;
            }
            cp16(aAddr + swz(row, col) * 16, src, pb);
        }
#pragma unroll
        for (int rep = 0; rep < 10; rep++) {
            int idx = tid + rep * 256;
            int row = idx >> 4, col = idx & 15;          // row 0..159
            int grow = (row >> 5) * 512 + j0 + (row & 31);
            cp16(bAddr + swz(row, col) * 16,
                 &g_Wcs[(size_t)grow * 512 + kc * 16 + col], 16);
        }
        cp_commit();
    };

    issue(0);
    for (int kc = 0; kc < 32; kc++) {
        if (kc + 1 < 32) issue(kc + 1);
        cp_wait(kc + 1 < 32);     // keep the just-issued group in flight
        __syncthreads();

        int st = kc & 1;
        const uint4* cA = dyn + st * 1024;
        const uint4* cB = dyn + 2048 + st * 2560;
#pragma unroll
        for (int t = 0; t < 2; t++) {
            uint4 A0 = cA[swz(mw * 16 + r,     t * 8 + q)];
            uint4 A1 = cA[swz(mw * 16 + r + 8, t * 8 + q)];
            uint4 A2 = cA[swz(mw * 16 + r,     t * 8 + q + 4)];
            uint4 A3 = cA[swz(mw * 16 + r + 8, t * 8 + q + 4)];
            uint32_t a1f[4] = {A0.x, A1.x, A2.x, A3.x};
            uint32_t a2f[4] = {A0.y, A1.y, A2.y, A3.y};
            uint32_t a3f[4] = {A0.z, A1.z, A2.z, A3.z};
#pragma unroll
            for (int g = 0; g < 5; g++) {
#pragma unroll
                for (int jt = 0; jt < 2; jt++) {
                    int col = jw * 16 + jt * 8 + r;
                    uint4 B0 = cB[swz(g * 32 + col, t * 8 + q)];
                    uint4 B1 = cB[swz(g * 32 + col, t * 8 + q + 4)];
                    float* d = acc[g][jt];
                    mma16816(d, a1f, B0.x, B1.x);   // h1*b1
                    mma16816(d, a1f, B0.y, B1.y);   // h1*b2
                    mma16816(d, a2f, B0.x, B1.x);   // h2*b1
                    mma16816(d, a1f, B0.z, B1.z);   // h1*b3
                    mma16816(d, a2f, B0.y, B1.y);   // h2*b2
                    mma16816(d, a3f, B0.x, B1.x);   // h3*b1
                }
            }
        }
        __syncthreads();
    }

    // ------- epilogue: gates -> (h,c) comp + logit partial per 16-j slice ----
#pragma unroll
    for (int half = 0; half < 2; half++) {
        int lrow = mw * 16 + r + half * 8;
        int b = sb[lrow];
        float partial = 0.f;
        if (b >= 0) {
            int ls = sls[lrow], rs = srs[lrow];
            size_t ob = ((size_t)((b << 5) + ls)) * 512;
            size_t rb = ((size_t)((b << 5) + rs)) * 512;
#pragma unroll
            for (int jt = 0; jt < 2; jt++) {
#pragma unroll
                for (int e = 0; e < 2; e++) {
                    int j    = j0 + jw * 16 + jt * 8 + q * 2 + e;
                    int ridx = half * 2 + e;
                    float iv = acc[0][jt][ridx] + bc[0 * 512 + j];
                    float fl = acc[1][jt][ridx] + bc[1 * 512 + j];
                    float fr = acc[2][jt][ridx] + bc[2 * 512 + j];
                    float uu = acc[3][jt][ridx] + bc[3 * 512 + j];
                    float oo = acc[4][jt][ridx] + bc[4 * 512 + j];
                    float cl = g_c[ob + j];
                    float cr = g_c[rb + j];
                    float cn = cl * sigf(fl + 1.f) + cr * sigf(fr + 1.f)
                             + tanhf(uu) * sigf(iv);
                    float hn = sigf(oo) * tanhf(cn);
                    g_compc[ob + j] = cn;
                    g_comph[ob + j] = hn;
                    partial += cq[j] * hn;
                }
            }
        }
        partial += __shfl_xor_sync(0xffffffffu, partial, 1);
        partial += __shfl_xor_sync(0xffffffffu, partial, 2);
        if (q == 0 && b >= 0) {
            int ls = sls[lrow];
            g_lgpart[((b << 5) + ls) * 32 + blockIdx.y * 2 + jw] = partial;
        }
    }
}

// ---------------- stable task compaction (1 block, deterministic) -----------
__global__ __launch_bounds__(512) void compact_kernel() {
    __shared__ int scan[512];
    int tid = threadIdx.x;
    int4 tk = g_tasks[tid];
    int v = tk.x ? 1 : 0;
    scan[tid] = v;
    __syncthreads();
    for (int off = 1; off < 512; off <<= 1) {
        int add = (tid >= off) ? scan[tid - off] : 0;
        __syncthreads();
        scan[tid] += add;
        __syncthreads();
    }
    if (v) g_ctasks[scan[tid] - 1] = tk;
    if (tid == 511) g_ntasks = scan[511];
}

// ---------------- split-K step GEMM (compacted tasks) -----------------------
// grid (8, 16, 4): row-block, j-block, k-split. Row-blocks beyond ntasks exit.
__global__ __launch_bounds__(256, 2) void gemm_step() {
    extern __shared__ uint4 dyn[];
    int*   sb  = (int*)(dyn + 7168);
    int*   sls = sb + 64;
    int*   srs = sls + 64;
    uint32_t sbase = (uint32_t)__cvta_generic_to_shared(dyn);

    int tid  = threadIdx.x;
    int row0 = blockIdx.x * 64;
    int j0   = blockIdx.y * 32;
    int ks   = blockIdx.z;
    int kbeg = ks * 8, kend = kbeg + 8;

    int n = g_ntasks;
    if (row0 >= n) return;            // uniform early exit: no B loads issued

    if (tid < 64) {
        int t = row0 + tid;
        int b = -1, ls = 0, rs = 0;
        if (t < n) { int4 tk = g_ctasks[t]; b = tk.y; ls = tk.z; rs = tk.w; }
        sb[tid] = b; sls[tid] = ls; srs[tid] = rs;
    }
    __syncthreads();

    int lane = tid & 31;
    int warp = tid >> 5;
    int mw = warp & 3;
    int jw = warp >> 2;
    int r = lane >> 2, q = lane & 3;

    float acc[5][2][4];
#pragma unroll
    for (int g = 0; g < 5; g++)
#pragma unroll
        for (int jt = 0; jt < 2; jt++)
#pragma unroll
            for (int e = 0; e < 4; e++) { acc[g][jt][e] = 0.f; }

    auto issue = [&](int kc) {
        int st = kc & 1;
        uint32_t aAddr = sbase + st * 1024 * 16;
        uint32_t bAddr = sbase + (2048 + st * 2560) * 16;
        int left  = (kc < 16);
        int pbase = (kc & 15) * 16;
#pragma unroll
        for (int rep = 0; rep < 4; rep++) {
            int idx = tid + rep * 256;
            int row = idx >> 4, col = idx & 15;
            int b = sb[row];
            const void* src = &g_Wcs[0];
            int pb = 0;
            if (b >= 0) {
                int slot = left ? sls[row] : srs[row];
                src = &g_hs[((size_t)((b << 5) + slot)) * 256 + pbase + col];
                pb = 16;
            }
            cp16(aAddr + swz(row, col) * 16, src, pb);
        }
#pragma unroll
        for (int rep = 0; rep < 10; rep++) {
            int idx = tid + rep * 256;
            int row = idx >> 4, col = idx & 15;
            int grow = (row >> 5) * 512 + j0 + (row & 31);
            cp16(bAddr + swz(row, col) * 16,
                 &g_Wcs[(size_t)grow * 512 + kc * 16 + col], 16);
        }
        cp_commit();
    };

    issue(kbeg);
    for (int kc = kbeg; kc < kend; kc++) {
        if (kc + 1 < kend) issue(kc + 1);
        cp_wait(kc + 1 < kend);
        __syncthreads();

        int st = kc & 1;
        const uint4* cA = dyn + st * 1024;
        const uint4* cB = dyn + 2048 + st * 2560;
#pragma unroll
        for (int t = 0; t < 2; t++) {
            uint4 A0 = cA[swz(mw * 16 + r,     t * 8 + q)];
            uint4 A1 = cA[swz(mw * 16 + r + 8, t * 8 + q)];
            uint4 A2 = cA[swz(mw * 16 + r,     t * 8 + q + 4)];
            uint4 A3 = cA[swz(mw * 16 + r + 8, t * 8 + q + 4)];
            uint32_t a1f[4] = {A0.x, A1.x, A2.x, A3.x};
            uint32_t a2f[4] = {A0.y, A1.y, A2.y, A3.y};
            uint32_t a3f[4] = {A0.z, A1.z, A2.z, A3.z};
#pragma unroll
            for (int g = 0; g < 5; g++) {
#pragma unroll
                for (int jt = 0; jt < 2; jt++) {
                    int col = jw * 16 + jt * 8 + r;
                    uint4 B0 = cB[swz(g * 32 + col, t * 8 + q)];
                    uint4 B1 = cB[swz(g * 32 + col, t * 8 + q + 4)];
                    float* d = acc[g][jt];
                    mma16816(d, a1f, B0.x, B1.x);
                    mma16816(d, a1f, B0.y, B1.y);
                    mma16816(d, a2f, B0.x, B1.x);
                    mma16816(d, a1f, B0.z, B1.z);
                    mma16816(d, a2f, B0.y, B1.y);
                    mma16816(d, a3f, B0.x, B1.x);
                }
            }
        }
        __syncthreads();
    }

    // write raw partials: g_part[(ks*512 + ctask)*2560 + g*512 + j]
#pragma unroll
    for (int half = 0; half < 2; half++) {
        int lrow = mw * 16 + r + half * 8;
        if (sb[lrow] >= 0) {
            size_t base = ((size_t)(ks * 512 + row0 + lrow)) * 2560;
#pragma unroll
            for (int g = 0; g < 5; g++)
#pragma unroll
                for (int jt = 0; jt < 2; jt++) {
                    int jbase = j0 + jw * 16 + jt * 8 + q * 2;
                    *(float2*)&g_part[base + g * 512 + jbase] =
                        make_float2(acc[g][jt][half * 2], acc[g][jt][half * 2 + 1]);
                }
        }
    }
}

// ---------------- reduce partials + gate epilogue (one block per ctask) -----
__global__ __launch_bounds__(256) void reduce_step(const float* __restrict__ bc,
                                                   const float* __restrict__ cq) {
    __shared__ float sp[2][256];
    int t = blockIdx.x;
    if (t >= g_ntasks) return;
    int4 tk = g_ctasks[t];
    int b = tk.y, ls = tk.z, rs = tk.w;
    int tid = threadIdx.x;
    size_t ob  = ((size_t)((b << 5) + ls)) * 512;
    size_t rbs = ((size_t)((b << 5) + rs)) * 512;

#pragma unroll
    for (int half = 0; half < 2; half++) {
        int j = tid + half * 256;
        float v[5];
#pragma unroll
        for (int g = 0; g < 5; g++) {
            size_t base = (size_t)t * 2560 + g * 512 + j;
            float s0 = g_part[base];
            float s1 = g_part[(size_t)512  * 2560 + base];
            float s2 = g_part[(size_t)1024 * 2560 + base];
            float s3 = g_part[(size_t)1536 * 2560 + base];
            v[g] = ((s0 + s1) + (s2 + s3)) + bc[g * 512 + j];
        }
        float cl = g_c[ob + j], cr = g_c[rbs + j];
        float cn = cl * sigf(v[1] + 1.f) + cr * sigf(v[2] + 1.f)
                 + tanhf(v[3]) * sigf(v[0]);
        float hn = sigf(v[4]) * tanhf(cn);
        g_compc[ob + j] = cn;
        g_comph[ob + j] = hn;
        sp[half][tid] = cq[j] * hn;
    }
    __syncthreads();
    // 32 slices of 16 j each, fixed-order sums (deterministic)
    if (tid < 32) {
        int half = tid >> 4, s16 = tid & 15;
        float s = 0.f;
#pragma unroll
        for (int k = 0; k < 16; k++) s += sp[half][s16 * 16 + k];
        g_lgpart[((b << 5) + ls) * 32 + tid] = s;
    }
}

// ---------------- select + merge (1 CTA per batch) --------------------------
__global__ __launch_bounds__(256) void select_kernel(const int* __restrict__ length,
                                                     int step) {
    int b = blockIdx.x;
    int lane = threadIdx.x & 31;
    int warp = threadIdx.x >> 5;
    __shared__ int sh_active, sh_s;

    if (warp == 0) {
        int len = length[b];
        int active = (step + 1 < len);
        int s = 0;
        if (active) {
            int n    = 32 - step;
            int vlim = len - step - 1;
            int myslot = (lane < n) ? g_order[(b << 5) + lane] : 0;

            float lg = -1e30f;
            if (lane < vlim) {            // deterministic fixed-order sum
                const float* p = &g_lgpart[((b << 5) + myslot) * 32];
                float sum = 0.f;
#pragma unroll
                for (int t = 0; t < 32; t++) sum += p[t];
                lg = sum * 0.04419417382415922f;   // 1/sqrt(512)
            }

            // argmax, first occurrence on ties (matches jnp.argmax)
            float bv = lg; int bi = lane;
#pragma unroll
            for (int off = 16; off; off >>= 1) {
                float ov = __shfl_down_sync(0xffffffffu, bv, off);
                int   oi = __shfl_down_sync(0xffffffffu, bi, off);
                if (ov > bv || (ov == bv && oi < bi)) { bv = ov; bi = oi; }
            }
            int p = __shfl_sync(0xffffffffu, bi, 0);

            s        = __shfl_sync(0xffffffffu, myslot, p);
            int prev = __shfl_sync(0xffffffffu, myslot, (p > 0) ? (p - 1) : 0);
            int nxt2 = __shfl_sync(0xffffffffu, myslot, (p + 2 <= n - 1) ? (p + 2) : 0);
            int nxt  = __shfl_down_sync(0xffffffffu, myslot, 1);

            if (lane >= p + 1 && lane <= n - 2) g_order[(b << 5) + lane] = nxt;
            if (lane == 0) {
                int4 t0 = make_int4(0, 0, 0, 0), t1 = make_int4(0, 0, 0, 0);
                if (p > 0)          t0 = make_int4(1, b, prev, s);
                if (p + 2 <= n - 1) t1 = make_int4(1, b, s, nxt2);
                g_tasks[2 * b]     = t0;
                g_tasks[2 * b + 1] = t1;
            }
        } else if (lane == 0) {
            g_tasks[2 * b]     = make_int4(0, 0, 0, 0);
            g_tasks[2 * b + 1] = make_int4(0, 0, 0, 0);
        }
        if (lane == 0) { sh_active = active; sh_s = s; }
    }
    __syncthreads();
    if (!sh_active) return;

    // merge: node s takes composed value; refresh fp32 + pre-split forms
    int t = threadIdx.x;
    size_t base = ((size_t)((b << 5) + sh_s)) * 512;
    float2 hp = *(const float2*)&g_comph[base + 2 * t];
    float2 cp = *(const float2*)&g_compc[base + 2 * t];
    *(float2*)&g_h[base + 2 * t] = hp;
    *(float2*)&g_c[base + 2 * t] = cp;
    g_hs[((size_t)((b << 5) + sh_s)) * 256 + t] = split3(hp.x, hp.y);
}

// ---------------- output: h of slot 0 of each batch -------------------------
__global__ void out_kernel(float* __restrict__ out) {
    int idx = blockIdx.x * 256 + threadIdx.x;   // 131072 total
    int b = idx >> 9, j = idx & 511;
    out[idx] = g_h[((size_t)b << 14) + j];      // slot 0
}

// ---------------- launch ----------------------------------------------------
extern "C" void kernel_launch(void* const* d_in, const int* in_sizes, int n_in,
                              void* d_out, int out_size) {
    const float* x      = (const float*)d_in[0];
    const int*   length = (const int*)  d_in[1];
    const float* Ww     = (const float*)d_in[2];
    const float* bw     = (const float*)d_in[3];
    const float* Wc     = (const float*)d_in[4];
    const float* bc     = (const float*)d_in[5];
    const float* cq     = (const float*)d_in[6];

    int shmem = 7168 * (int)sizeof(uint4) + 3 * 64 * (int)sizeof(int);  // 115456 B
    static int configured = 0;
    if (!configured) {
        cudaFuncSetAttribute(compose_mma,
                             cudaFuncAttributeMaxDynamicSharedMemorySize, shmem);
        cudaFuncSetAttribute(gemm_step,
                             cudaFuncAttributeMaxDynamicSharedMemorySize, shmem);
        configured = 1;
    }

    init_kernel<<<32, 256>>>();
    split_wc_kernel<<<5120, 256>>>(Wc);
    word_kernel<<<dim3(64, 8), 256>>>(x, Ww, bw);
    // initial compose of all 31 adjacent pairs per batch (7936 rows)
    compose_mma<<<dim3(124, 16), 256, shmem>>>(bc, cq, 1, 7936);
    for (int i = 0; i < 31; i++) {
        select_kernel<<<256, 256>>>(length, i);
        compact_kernel<<<1, 512>>>();
        gemm_step<<<dim3(8, 16, 4), 256, shmem>>>();
        reduce_step<<<512, 256>>>(bc, cq);
    }
    out_kernel<<<512, 256>>>((float*)d_out);
    (void)in_sizes; (void)n_in; (void)out_size;
}